// round 2
// baseline (speedup 1.0000x reference)
#include <cuda_runtime.h>
#include <cstdint>

#define Bsz 128
#define Lseq 1024
#define Cin 256
#define Hd 256
#define G3 768   // 3*H
#define RBLK 128 // persistent recurrence blocks (<= 148 SMs, guaranteed co-resident)

// ---------------- scratch (static device globals; no allocation) ----------------
__device__ float g_gi[(size_t)Lseq * G3 * Bsz];      // [t][3H][B]  ~403MB
__device__ float g_hseq0[(size_t)Lseq * Hd * Bsz];   // [t][H][B]   ~134MB
__device__ float g_hseq1[(size_t)Lseq * Hd * Bsz];   // [t][H][B]   ~134MB

__device__ unsigned g_bar_count = 0;
__device__ volatile unsigned g_bar_gen = 0;

// ---------------- input-side GEMM: Gi[t][c][b] = dot(Xrow(t,b), W[c,:]) + bias[c] -----
// grid: (6, 1024). block tile: 128 c  x 128 b, K=256, BK=16, 256 threads, 8x8/thread.
__global__ __launch_bounds__(256) void gi_gemm_kernel(
    const float* __restrict__ xin,      // layer0: x [B][L][C]
    const float* __restrict__ W,        // [3H][K] row-major, K=256
    const float* __restrict__ bias,     // [3H]
    int layer)
{
    __shared__ float Ws[16 * 132];
    __shared__ float As[16 * 132];

    const int t  = blockIdx.y;
    const int c0 = blockIdx.x * 128;
    const int tid = threadIdx.x;
    const int ty = tid >> 4;   // 0..15
    const int tx = tid & 15;   // 0..15

    float acc[8][8];
#pragma unroll
    for (int i = 0; i < 8; i++)
#pragma unroll
        for (int j = 0; j < 8; j++) acc[i][j] = 0.0f;

    for (int k0 = 0; k0 < 256; k0 += 16) {
        // ---- load W tile (128c x 16k), store transposed Ws[k][c]
        {
            int row  = tid >> 2;
            int col4 = (tid & 3) * 4;
#pragma unroll
            for (int it = 0; it < 2; it++, row += 64) {
                float4 w = *(const float4*)(W + (size_t)(c0 + row) * 256 + k0 + col4);
                Ws[(col4 + 0) * 132 + row] = w.x;
                Ws[(col4 + 1) * 132 + row] = w.y;
                Ws[(col4 + 2) * 132 + row] = w.z;
                Ws[(col4 + 3) * 132 + row] = w.w;
            }
        }
        // ---- load A tile (16k x 128b) into As[k][b]
        if (layer == 0) {
            int row  = tid >> 2;          // b
            int col4 = (tid & 3) * 4;     // k
#pragma unroll
            for (int it = 0; it < 2; it++, row += 64) {
                float4 a = *(const float4*)(xin + ((size_t)row * Lseq + t) * 256 + k0 + col4);
                As[(col4 + 0) * 132 + row] = a.x;
                As[(col4 + 1) * 132 + row] = a.y;
                As[(col4 + 2) * 132 + row] = a.z;
                As[(col4 + 3) * 132 + row] = a.w;
            }
        } else {
            // A row (t,b): g_hseq0[t][k][b] — already [k][b] contiguous in b
            int idx = tid;
#pragma unroll
            for (int it = 0; it < 2; it++, idx += 256) {
                int k  = idx >> 5;          // 0..15
                int b4 = (idx & 31) * 4;    // 0..124
                float4 a = *(const float4*)(g_hseq0 + (size_t)t * Hd * Bsz
                                            + (size_t)(k0 + k) * Bsz + b4);
                *(float4*)(As + k * 132 + b4) = a;
            }
        }
        __syncthreads();

#pragma unroll
        for (int kk = 0; kk < 16; kk++) {
            float wr[8], ar[8];
            *(float4*)(wr)     = *(const float4*)(Ws + kk * 132 + ty * 4);
            *(float4*)(wr + 4) = *(const float4*)(Ws + kk * 132 + 64 + ty * 4);
            *(float4*)(ar)     = *(const float4*)(As + kk * 132 + tx * 4);
            *(float4*)(ar + 4) = *(const float4*)(As + kk * 132 + 64 + tx * 4);
#pragma unroll
            for (int i = 0; i < 8; i++)
#pragma unroll
                for (int j = 0; j < 8; j++)
                    acc[i][j] += wr[i] * ar[j];
        }
        __syncthreads();
    }

    // ---- epilogue: add bias, write Gi[t][c][b]
    float* gout = g_gi + (size_t)t * G3 * Bsz;
#pragma unroll
    for (int i = 0; i < 8; i++) {
        int c = (i < 4) ? (c0 + ty * 4 + i) : (c0 + 64 + ty * 4 + (i - 4));
        float bv = bias[c];
        float4 o1 = make_float4(acc[i][0] + bv, acc[i][1] + bv, acc[i][2] + bv, acc[i][3] + bv);
        float4 o2 = make_float4(acc[i][4] + bv, acc[i][5] + bv, acc[i][6] + bv, acc[i][7] + bv);
        *(float4*)(gout + (size_t)c * Bsz + tx * 4)      = o1;
        *(float4*)(gout + (size_t)c * Bsz + 64 + tx * 4) = o2;
    }
}

// ---------------- persistent GRU recurrence, one layer ----------------
// 128 blocks = 4 batch-tiles(32) x 32 hidden-tiles(8 units -> 24 gate cols).
// Weight slice (24x256 fp32 = 24KB) persistent in SMEM; h tile staged per step.
__global__ __launch_bounds__(256) void gru_recur_kernel(
    const float* __restrict__ w_hh,   // [3H][H]
    const float* __restrict__ b_hh,   // [3H]
    const float* __restrict__ h0all,  // [NL][B][H]
    int layer)
{
    extern __shared__ float sm[];
    float* w_s  = sm;                 // 6144 floats: [g*8+j][k]
    float* h_s  = sm + 6144;          // 8192 floats: [k][b] (k-major, 32 b)
    float* bh_s = sm + 6144 + 8192;   // 24 floats

    const int tid = threadIdx.x;
    const int bt = blockIdx.x >> 5;   // 0..3
    const int ht = blockIdx.x & 31;   // 0..31
    const int b0 = bt * 32;
    const int j0 = ht * 8;

    float* hseq = layer ? g_hseq1 : g_hseq0;

    // load persistent weight slice (coalesced along k)
    for (int idx = tid; idx < 6144; idx += 256) {
        int gj = idx >> 8;            // 0..23
        int k  = idx & 255;
        int g  = gj >> 3, j = gj & 7;
        w_s[idx] = w_hh[(size_t)(g * 256 + j0 + j) * 256 + k];
    }
    if (tid < 24) {
        int g = tid >> 3, j = tid & 7;
        bh_s[tid] = b_hh[g * 256 + j0 + j];
    }

    unsigned gen = g_bar_gen;  // monotonic across launches/replays; consistent at entry
    __syncthreads();

    const int j = tid >> 5;    // hidden unit within tile (warp-uniform)
    const int b = tid & 31;    // batch lane
    const float* wr = w_s + (0 * 8 + j) * 256;
    const float* wz = w_s + (1 * 8 + j) * 256;
    const float* wn = w_s + (2 * 8 + j) * 256;

    for (int t = 0; t < Lseq; t++) {
        // stage h_prev[b0..b0+32)[0..256) into h_s[k][b]
        if (t == 0) {
            const float* h0g = h0all + (size_t)layer * Bsz * Hd;
            for (int idx = tid; idx < 8192; idx += 256) {
                int k = idx >> 5, bb = idx & 31;
                h_s[idx] = h0g[(size_t)(b0 + bb) * 256 + k];
            }
        } else {
            const float* src = hseq + (size_t)(t - 1) * Hd * Bsz;
            for (int idx = tid; idx < 8192; idx += 256) {
                int k = idx >> 5, bb = idx & 31;
                h_s[idx] = src[k * Bsz + b0 + bb];   // coalesced 128B per warp
            }
        }
        __syncthreads();

        // gh = h_prev . w_hh^T  for this thread's (b, j): 3 dots of K=256
        float ar0 = 0.f, ar1 = 0.f, az0 = 0.f, az1 = 0.f, an0 = 0.f, an1 = 0.f;
#pragma unroll 8
        for (int k0 = 0; k0 < 256; k0 += 4) {
            float4 w4r = *(const float4*)(wr + k0);  // warp-broadcast
            float4 w4z = *(const float4*)(wz + k0);
            float4 w4n = *(const float4*)(wn + k0);
            float h0v = h_s[(k0 + 0) * 32 + b];      // conflict-free, lanes = b
            float h1v = h_s[(k0 + 1) * 32 + b];
            float h2v = h_s[(k0 + 2) * 32 + b];
            float h3v = h_s[(k0 + 3) * 32 + b];
            ar0 += h0v * w4r.x; ar0 += h1v * w4r.y;
            ar1 += h2v * w4r.z; ar1 += h3v * w4r.w;
            az0 += h0v * w4z.x; az0 += h1v * w4z.y;
            az1 += h2v * w4z.z; az1 += h3v * w4z.w;
            an0 += h0v * w4n.x; an0 += h1v * w4n.y;
            an1 += h2v * w4n.z; an1 += h3v * w4n.w;
        }
        float gr = ar0 + ar1 + bh_s[j];
        float gz = az0 + az1 + bh_s[8 + j];
        float gn = an0 + an1 + bh_s[16 + j];

        const float* gi_t = g_gi + (size_t)t * G3 * Bsz;
        float ir  = gi_t[(size_t)(0 * 256 + j0 + j) * Bsz + b0 + b];
        float iz  = gi_t[(size_t)(1 * 256 + j0 + j) * Bsz + b0 + b];
        float inn = gi_t[(size_t)(2 * 256 + j0 + j) * Bsz + b0 + b];

        float r = 1.0f / (1.0f + __expf(-(ir + gr)));
        float z = 1.0f / (1.0f + __expf(-(iz + gz)));
        float n = tanhf(inn + r * gn);
        float hprev = h_s[(j0 + j) * 32 + b];
        float hnew = (1.0f - z) * n + z * hprev;

        hseq[(size_t)t * Hd * Bsz + (size_t)(j0 + j) * Bsz + b0 + b] = hnew;

        // ---- software grid barrier (all RBLK blocks resident) ----
        __syncthreads();
        if (tid == 0) {
            __threadfence();
            unsigned target = gen + 1;
            if (atomicAdd(&g_bar_count, 1u) == RBLK - 1) {
                atomicExch(&g_bar_count, 0u);
                __threadfence();
                g_bar_gen = target;
            } else {
                while (g_bar_gen < target) { }
            }
        }
        gen++;
        __syncthreads();
    }
}

// ---------------- transpose g_hseq1 [t][h][b] -> out [b][t][h] ----------------
__global__ __launch_bounds__(256) void transpose_out_kernel(float* __restrict__ out)
{
    __shared__ float tile[32 * 129];
    const int t  = blockIdx.y;
    const int h0 = blockIdx.x * 32;
    const int tid = threadIdx.x;
    const float* src = g_hseq1 + (size_t)t * Hd * Bsz + (size_t)h0 * Bsz;

    for (int idx = tid; idx < 4096; idx += 256) {
        int hh = idx >> 7, bb = idx & 127;
        tile[hh * 129 + bb] = src[idx];
    }
    __syncthreads();
    for (int idx = tid; idx < 4096; idx += 256) {
        int bb = idx >> 5, hh = idx & 31;
        out[(size_t)bb * Lseq * Hd + (size_t)t * Hd + h0 + hh] = tile[hh * 129 + bb];
    }
}

// ---------------- final hidden states: out[B*L*H + layer*B*H + b*H + h] ----------------
__global__ __launch_bounds__(256) void hn_kernel(float* __restrict__ out)
{
    int idx = blockIdx.x * blockDim.x + threadIdx.x;   // 0..65535
    int layer = idx >> 15;
    int b = (idx >> 8) & 127;
    int h = idx & 255;
    const float* hs = layer ? g_hseq1 : g_hseq0;
    out[(size_t)Bsz * Lseq * Hd + idx] = hs[(size_t)(Lseq - 1) * Hd * Bsz + (size_t)h * Bsz + b];
}

// ---------------- launcher ----------------
extern "C" void kernel_launch(void* const* d_in, const int* in_sizes, int n_in,
                              void* d_out, int out_size)
{
    const float* x     = (const float*)d_in[0];
    const float* h0    = (const float*)d_in[1];
    const float* w_ih0 = (const float*)d_in[2];
    const float* w_hh0 = (const float*)d_in[3];
    const float* b_ih0 = (const float*)d_in[4];
    const float* b_hh0 = (const float*)d_in[5];
    const float* w_ih1 = (const float*)d_in[6];
    const float* w_hh1 = (const float*)d_in[7];
    const float* b_ih1 = (const float*)d_in[8];
    const float* b_hh1 = (const float*)d_in[9];
    float* out = (float*)d_out;

    const size_t smem = (6144 + 8192 + 32) * sizeof(float);  // ~57.5 KB dynamic
    cudaFuncSetAttribute(gru_recur_kernel,
                         cudaFuncAttributeMaxDynamicSharedMemorySize, (int)smem);

    // layer 0
    gi_gemm_kernel<<<dim3(6, Lseq), 256>>>(x, w_ih0, b_ih0, 0);
    gru_recur_kernel<<<RBLK, 256, smem>>>(w_hh0, b_hh0, h0, 0);
    // layer 1 (input = g_hseq0)
    gi_gemm_kernel<<<dim3(6, Lseq), 256>>>(x, w_ih1, b_ih1, 1);
    gru_recur_kernel<<<RBLK, 256, smem>>>(w_hh1, b_hh1, h0, 1);
    // outputs
    transpose_out_kernel<<<dim3(8, Lseq), 256>>>(out);
    if (out_size >= (int)((size_t)Bsz * Lseq * Hd + 2 * Bsz * Hd))
        hn_kernel<<<256, 256>>>(out);
}

// round 3
// speedup vs baseline: 1.2610x; 1.2610x over previous
#include <cuda_runtime.h>
#include <cstdint>

#define Bsz 128
#define Lseq 1024
#define Cin 256
#define Hd 256
#define G3 768
#define RBLK 128

typedef unsigned long long u64;

__device__ __forceinline__ u64 f2fma(u64 a, u64 b, u64 c) {
    u64 d; asm("fma.rn.f32x2 %0, %1, %2, %3;" : "=l"(d) : "l"(a), "l"(b), "l"(c)); return d;
}
__device__ __forceinline__ u64 dup2(float x) {
    u64 r; asm("mov.b64 %0, {%1, %1};" : "=l"(r) : "f"(x)); return r;
}
__device__ __forceinline__ void up2(u64 v, float& lo, float& hi) {
    asm("mov.b64 {%0, %1}, %2;" : "=f"(lo), "=f"(hi) : "l"(v));
}

// ---------------- scratch ----------------
// g_gi: [t][3H][B]
// g_hseq*: pair-interleaved [t][k2=128][b=128][2]  (element (t,k,b) at t*32768 + (k>>1)*256 + b*2 + (k&1))
__device__ float g_gi[(size_t)Lseq * G3 * Bsz];
__device__ float g_hseq0[(size_t)Lseq * Hd * Bsz];
__device__ float g_hseq1[(size_t)Lseq * Hd * Bsz];

__device__ unsigned g_bar_count = 0;
__device__ volatile unsigned g_bar_gen = 0;

// ---------------- input-side GEMM: Gi[t][c][b] ----------------
__global__ __launch_bounds__(256) void gi_gemm_kernel(
    const float* __restrict__ xin, const float* __restrict__ W,
    const float* __restrict__ bias, int layer)
{
    __shared__ float Ws[16 * 132];
    __shared__ float As[16 * 132];

    const int t  = blockIdx.y;
    const int c0 = blockIdx.x * 128;
    const int tid = threadIdx.x;
    const int ty = tid >> 4;
    const int tx = tid & 15;

    u64 acc2[8][4];
#pragma unroll
    for (int i = 0; i < 8; i++)
#pragma unroll
        for (int j = 0; j < 4; j++) acc2[i][j] = 0ull;

    for (int k0 = 0; k0 < 256; k0 += 16) {
        // W tile (128c x 16k) -> Ws[k][c]
        {
            int row  = tid >> 2;
            int col4 = (tid & 3) * 4;
#pragma unroll
            for (int it = 0; it < 2; it++, row += 64) {
                float4 w = *(const float4*)(W + (size_t)(c0 + row) * 256 + k0 + col4);
                Ws[(col4 + 0) * 132 + row] = w.x;
                Ws[(col4 + 1) * 132 + row] = w.y;
                Ws[(col4 + 2) * 132 + row] = w.z;
                Ws[(col4 + 3) * 132 + row] = w.w;
            }
        }
        // A tile (16k x 128b) -> As[k][b]
        if (layer == 0) {
            int row  = tid >> 2;
            int col4 = (tid & 3) * 4;
#pragma unroll
            for (int it = 0; it < 2; it++, row += 64) {
                float4 a = *(const float4*)(xin + ((size_t)row * Lseq + t) * 256 + k0 + col4);
                As[(col4 + 0) * 132 + row] = a.x;
                As[(col4 + 1) * 132 + row] = a.y;
                As[(col4 + 2) * 132 + row] = a.z;
                As[(col4 + 3) * 132 + row] = a.w;
            }
        } else {
            // g_hseq0 pair layout: float4 at ((t*128 + k2)*128 + b)*2 covers
            // {h[2k2][b], h[2k2+1][b], h[2k2][b+1], h[2k2+1][b+1]}
#pragma unroll
            for (int it = 0; it < 2; it++) {
                int idx = tid + it * 256;             // 0..511
                int k2l = idx >> 6;                   // 0..7
                int bp  = idx & 63;                   // b pair
                float4 v = *(const float4*)(g_hseq0 + ((size_t)t * 128 + (k0 >> 1) + k2l) * 256 + bp * 4);
                As[(2 * k2l + 0) * 132 + 2 * bp]     = v.x;
                As[(2 * k2l + 1) * 132 + 2 * bp]     = v.y;
                As[(2 * k2l + 0) * 132 + 2 * bp + 1] = v.z;
                As[(2 * k2l + 1) * 132 + 2 * bp + 1] = v.w;
            }
        }
        __syncthreads();

#pragma unroll
        for (int kk = 0; kk < 16; kk++) {
            float wr[8];
            *(float4*)(wr)     = *(const float4*)(Ws + kk * 132 + ty * 4);
            *(float4*)(wr + 4) = *(const float4*)(Ws + kk * 132 + 64 + ty * 4);
            ulonglong2 aA = *(const ulonglong2*)(As + kk * 132 + tx * 4);
            ulonglong2 aB = *(const ulonglong2*)(As + kk * 132 + 64 + tx * 4);
            u64 ap0 = aA.x, ap1 = aA.y, ap2 = aB.x, ap3 = aB.y;
#pragma unroll
            for (int i = 0; i < 8; i++) {
                u64 wd = dup2(wr[i]);
                acc2[i][0] = f2fma(ap0, wd, acc2[i][0]);
                acc2[i][1] = f2fma(ap1, wd, acc2[i][1]);
                acc2[i][2] = f2fma(ap2, wd, acc2[i][2]);
                acc2[i][3] = f2fma(ap3, wd, acc2[i][3]);
            }
        }
        __syncthreads();
    }

    float* gout = g_gi + (size_t)t * G3 * Bsz;
#pragma unroll
    for (int i = 0; i < 8; i++) {
        int c = (i < 4) ? (c0 + ty * 4 + i) : (c0 + 64 + ty * 4 + (i - 4));
        float bv = bias[c];
        float a0, a1, a2, a3, a4, a5, a6, a7;
        up2(acc2[i][0], a0, a1); up2(acc2[i][1], a2, a3);
        up2(acc2[i][2], a4, a5); up2(acc2[i][3], a6, a7);
        float4 o1 = make_float4(a0 + bv, a1 + bv, a2 + bv, a3 + bv);
        float4 o2 = make_float4(a4 + bv, a5 + bv, a6 + bv, a7 + bv);
        *(float4*)(gout + (size_t)c * Bsz + tx * 4)      = o1;
        *(float4*)(gout + (size_t)c * Bsz + 64 + tx * 4) = o2;
    }
}

// ---------------- persistent GRU recurrence ----------------
// 128 blocks x 512 threads. Block tile: 32 batch x 8 hidden (24 gates).
// Thread: b = tid&31, j = (tid>>5)&7, kh = tid>>8 (K split in 2 halves).
__global__ __launch_bounds__(512) void gru_recur_kernel(
    const float* __restrict__ w_hh, const float* __restrict__ b_hh,
    const float* __restrict__ h0all, int layer)
{
    extern __shared__ float sm[];
    float* w_s   = sm;                    // 6144: [g*8+j][k]
    float* h2_s  = sm + 6144;             // 8192: pair (k2*32+b)*2
    float* red_s = sm + 6144 + 8192;      // 768
    float* bh_s  = sm + 6144 + 8192 + 768;// 24 (+pad)

    const int tid = threadIdx.x;
    const int bt = blockIdx.x >> 5;
    const int ht = blockIdx.x & 31;
    const int b0 = bt * 32;
    const int j0 = ht * 8;

    float* hseq = layer ? g_hseq1 : g_hseq0;

    // persistent weights (coalesced along k)
    for (int idx = tid; idx < 6144; idx += 512) {
        int gj = idx >> 8;
        int k  = idx & 255;
        int g  = gj >> 3, j = gj & 7;
        w_s[idx] = w_hh[(size_t)(g * 256 + j0 + j) * 256 + k];
    }
    if (tid < 24) {
        int g = tid >> 3, j = tid & 7;
        bh_s[tid] = b_hh[g * 256 + j0 + j];
    }

    unsigned gen = g_bar_gen;
    __syncthreads();

    const int b  = tid & 31;
    const int j  = (tid >> 5) & 7;
    const int kh = tid >> 8;
    const int jb = tid & 255;

    const float* wrp = w_s + (0 * 8 + j) * 256 + kh * 128;
    const float* wzp = wrp + 2048;
    const float* wnp = wrp + 4096;
    const float* hbase = h2_s + kh * 4096 + b * 2;

    // prefetch gi for t=0
    const size_t gidx = (size_t)(j0 + j) * Bsz + b0 + b;
    float cir = 0.f, ciz = 0.f, cin_ = 0.f;
    if (kh == 0) {
        cir  = g_gi[gidx];
        ciz  = g_gi[32768 + gidx];
        cin_ = g_gi[65536 + gidx];
    }

    for (int t = 0; t < Lseq; t++) {
        // ---- stage h_prev into h2_s (pair layout) ----
        if (t == 0) {
            const float* h0g = h0all + (size_t)layer * Bsz * Hd;
            for (int i = tid; i < 8192; i += 512) {
                int k = i >> 5, bb = i & 31;
                h2_s[(k >> 1) * 64 + bb * 2 + (k & 1)] = h0g[(size_t)(b0 + bb) * 256 + k];
            }
        } else {
            const float* srcT = hseq + (size_t)(t - 1) * (Hd * Bsz);
            for (int i = tid; i < 2048; i += 512) {
                int k2 = i >> 4;
                int bq = (i & 15) * 2;
                float4 v = *(const float4*)(srcT + (size_t)k2 * 256 + (size_t)(b0 + bq) * 2);
                *(float4*)(h2_s + k2 * 64 + bq * 2) = v;
            }
        }
        __syncthreads();

        // ---- partial dots over this thread's k-half (packed f32x2) ----
        u64 accr = 0ull, accz = 0ull, accn = 0ull;
#pragma unroll 8
        for (int i = 0; i < 64; i += 2) {
            u64 h2a = *(const u64*)(hbase + i * 64);
            u64 h2b = *(const u64*)(hbase + i * 64 + 64);
            ulonglong2 wr2 = *(const ulonglong2*)(wrp + 2 * i);
            ulonglong2 wz2 = *(const ulonglong2*)(wzp + 2 * i);
            ulonglong2 wn2 = *(const ulonglong2*)(wnp + 2 * i);
            accr = f2fma(h2a, wr2.x, accr); accr = f2fma(h2b, wr2.y, accr);
            accz = f2fma(h2a, wz2.x, accz); accz = f2fma(h2b, wz2.y, accz);
            accn = f2fma(h2a, wn2.x, accn); accn = f2fma(h2b, wn2.y, accn);
        }
        float sr, sz, sn;
        { float lo, hi;
          up2(accr, lo, hi); sr = lo + hi;
          up2(accz, lo, hi); sz = lo + hi;
          up2(accn, lo, hi); sn = lo + hi; }

        if (kh == 1) {
            red_s[jb]       = sr;
            red_s[256 + jb] = sz;
            red_s[512 + jb] = sn;
        }
        __syncthreads();

        if (kh == 0) {
            float gr = sr + red_s[jb]       + bh_s[j];
            float gz = sz + red_s[256 + jb] + bh_s[8 + j];
            float gn = sn + red_s[512 + jb] + bh_s[16 + j];
            float r = 1.0f / (1.0f + __expf(-(cir + gr)));
            float z = 1.0f / (1.0f + __expf(-(ciz + gz)));
            float n = tanhf(cin_ + r * gn);
            int jj = j0 + j;
            float hprev = h2_s[(jj >> 1) * 64 + b * 2 + (jj & 1)];
            float hnew = (1.0f - z) * n + z * hprev;
            hseq[(size_t)t * (Hd * Bsz) + (size_t)(jj >> 1) * 256 + (size_t)(b0 + b) * 2 + (jj & 1)] = hnew;
        }
        __syncthreads();

        // ---- arrive, prefetch next gi during barrier skew, then wait ----
        unsigned target = gen + 1;
        if (tid == 0) {
            __threadfence();
            if (atomicAdd(&g_bar_count, 1u) == RBLK - 1u) {
                atomicExch(&g_bar_count, 0u);
                __threadfence();
                g_bar_gen = target;
            }
        }
        if (kh == 0 && t + 1 < Lseq) {
            const float* gi_n = g_gi + (size_t)(t + 1) * (G3 * Bsz);
            cir  = gi_n[gidx];
            ciz  = gi_n[32768 + gidx];
            cin_ = gi_n[65536 + gidx];
        }
        if (tid == 0) {
            while (g_bar_gen != target) { }
        }
        gen = target;
        __syncthreads();
    }
}

// ---------------- transpose: g_hseq1 pair layout -> out [b][t][h] ----------------
__global__ __launch_bounds__(256) void transpose_out_kernel(float* __restrict__ out)
{
    __shared__ float tile[32 * 129];
    const int t  = blockIdx.y;
    const int h0 = blockIdx.x * 32;
    const int tid = threadIdx.x;
    const float* src = g_hseq1 + (size_t)t * (Hd * Bsz);

    for (int idx = tid; idx < 1024; idx += 256) {
        int k2l = idx >> 6;   // 0..15 -> h pair
        int bp  = idx & 63;   // b pair
        float4 v = *(const float4*)(src + ((size_t)(h0 >> 1) + k2l) * 256 + bp * 4);
        tile[(2 * k2l + 0) * 129 + 2 * bp]     = v.x;
        tile[(2 * k2l + 1) * 129 + 2 * bp]     = v.y;
        tile[(2 * k2l + 0) * 129 + 2 * bp + 1] = v.z;
        tile[(2 * k2l + 1) * 129 + 2 * bp + 1] = v.w;
    }
    __syncthreads();
    for (int idx = tid; idx < 4096; idx += 256) {
        int bb = idx >> 5, hh = idx & 31;
        out[(size_t)bb * Lseq * Hd + (size_t)t * Hd + h0 + hh] = tile[hh * 129 + bb];
    }
}

// ---------------- final hidden states ----------------
__global__ __launch_bounds__(256) void hn_kernel(float* __restrict__ out)
{
    int idx = blockIdx.x * blockDim.x + threadIdx.x;  // 0..65535
    int layer = idx >> 15;
    int b = (idx >> 8) & 127;
    int h = idx & 255;
    const float* hs = layer ? g_hseq1 : g_hseq0;
    out[(size_t)Bsz * Lseq * Hd + idx] =
        hs[(size_t)(Lseq - 1) * (Hd * Bsz) + (size_t)(h >> 1) * 256 + b * 2 + (h & 1)];
}

// ---------------- launcher ----------------
extern "C" void kernel_launch(void* const* d_in, const int* in_sizes, int n_in,
                              void* d_out, int out_size)
{
    const float* x     = (const float*)d_in[0];
    const float* h0    = (const float*)d_in[1];
    const float* w_ih0 = (const float*)d_in[2];
    const float* w_hh0 = (const float*)d_in[3];
    const float* b_ih0 = (const float*)d_in[4];
    const float* b_hh0 = (const float*)d_in[5];
    const float* w_ih1 = (const float*)d_in[6];
    const float* w_hh1 = (const float*)d_in[7];
    const float* b_ih1 = (const float*)d_in[8];
    const float* b_hh1 = (const float*)d_in[9];
    float* out = (float*)d_out;

    const size_t smem = (6144 + 8192 + 768 + 32) * sizeof(float);
    cudaFuncSetAttribute(gru_recur_kernel,
                         cudaFuncAttributeMaxDynamicSharedMemorySize, (int)smem);

    gi_gemm_kernel<<<dim3(6, Lseq), 256>>>(x, w_ih0, b_ih0, 0);
    gru_recur_kernel<<<RBLK, 512, smem>>>(w_hh0, b_hh0, h0, 0);
    gi_gemm_kernel<<<dim3(6, Lseq), 256>>>(x, w_ih1, b_ih1, 1);
    gru_recur_kernel<<<RBLK, 512, smem>>>(w_hh1, b_hh1, h0, 1);
    transpose_out_kernel<<<dim3(8, Lseq), 256>>>(out);
    if (out_size >= (int)((size_t)Bsz * Lseq * Hd + 2 * Bsz * Hd))
        hn_kernel<<<256, 256>>>(out);
}

// round 4
// speedup vs baseline: 1.5223x; 1.2072x over previous
#include <cuda_runtime.h>
#include <cstdint>

#define Bsz 128
#define Lseq 1024
#define Hd 256
#define G3 768
#define RBLK 128
#define W2S 258   // u64 stride per duplicated-weight row (256 + 2 pad -> 2064B, bank-staggered)

typedef unsigned long long u64;

__device__ __forceinline__ u64 f2fma(u64 a, u64 b, u64 c) {
    u64 d; asm("fma.rn.f32x2 %0, %1, %2, %3;" : "=l"(d) : "l"(a), "l"(b), "l"(c)); return d;
}
__device__ __forceinline__ u64 f2add(u64 a, u64 b) {
    u64 d; asm("add.rn.f32x2 %0, %1, %2;" : "=l"(d) : "l"(a), "l"(b)); return d;
}
__device__ __forceinline__ u64 dup2(float x) {
    u64 r; asm("mov.b64 %0, {%1, %1};" : "=l"(r) : "f"(x)); return r;
}
__device__ __forceinline__ void up2(u64 v, float& lo, float& hi) {
    asm("mov.b64 {%0, %1}, %2;" : "=f"(lo), "=f"(hi) : "l"(v));
}

// ---------------- scratch ----------------
// g_gi:   [t][3H][B]
// g_hseq: plain [t][k][b]
__device__ float g_gi[(size_t)Lseq * G3 * Bsz];
__device__ float g_hseq0[(size_t)Lseq * Hd * Bsz];
__device__ float g_hseq1[(size_t)Lseq * Hd * Bsz];

__device__ unsigned g_bar_count = 0;
__device__ volatile unsigned g_bar_gen = 0;

// ---------------- input-side GEMM: Gi[t][c][b] ----------------
__global__ __launch_bounds__(256) void gi_gemm_kernel(
    const float* __restrict__ xin, const float* __restrict__ W,
    const float* __restrict__ bias, int layer)
{
    __shared__ float Ws[16 * 132];
    __shared__ float As[16 * 132];

    const int t  = blockIdx.y;
    const int c0 = blockIdx.x * 128;
    const int tid = threadIdx.x;
    const int ty = tid >> 4;
    const int tx = tid & 15;

    u64 acc2[8][4];
#pragma unroll
    for (int i = 0; i < 8; i++)
#pragma unroll
        for (int j = 0; j < 4; j++) acc2[i][j] = 0ull;

    for (int k0 = 0; k0 < 256; k0 += 16) {
        {
            int row  = tid >> 2;
            int col4 = (tid & 3) * 4;
#pragma unroll
            for (int it = 0; it < 2; it++, row += 64) {
                float4 w = *(const float4*)(W + (size_t)(c0 + row) * 256 + k0 + col4);
                Ws[(col4 + 0) * 132 + row] = w.x;
                Ws[(col4 + 1) * 132 + row] = w.y;
                Ws[(col4 + 2) * 132 + row] = w.z;
                Ws[(col4 + 3) * 132 + row] = w.w;
            }
        }
        if (layer == 0) {
            int row  = tid >> 2;
            int col4 = (tid & 3) * 4;
#pragma unroll
            for (int it = 0; it < 2; it++, row += 64) {
                float4 a = *(const float4*)(xin + ((size_t)row * Lseq + t) * 256 + k0 + col4);
                As[(col4 + 0) * 132 + row] = a.x;
                As[(col4 + 1) * 132 + row] = a.y;
                As[(col4 + 2) * 132 + row] = a.z;
                As[(col4 + 3) * 132 + row] = a.w;
            }
        } else {
            // plain [t][k][b]
#pragma unroll
            for (int it = 0; it < 2; it++) {
                int idx = tid + it * 256;
                int k  = idx >> 5;
                int b4 = (idx & 31) * 4;
                float4 a = *(const float4*)(g_hseq0 + ((size_t)t * 256 + k0 + k) * 128 + b4);
                *(float4*)(As + k * 132 + b4) = a;
            }
        }
        __syncthreads();

#pragma unroll
        for (int kk = 0; kk < 16; kk++) {
            float wr[8];
            *(float4*)(wr)     = *(const float4*)(Ws + kk * 132 + ty * 4);
            *(float4*)(wr + 4) = *(const float4*)(Ws + kk * 132 + 64 + ty * 4);
            ulonglong2 aA = *(const ulonglong2*)(As + kk * 132 + tx * 4);
            ulonglong2 aB = *(const ulonglong2*)(As + kk * 132 + 64 + tx * 4);
#pragma unroll
            for (int i = 0; i < 8; i++) {
                u64 wd = dup2(wr[i]);
                acc2[i][0] = f2fma(aA.x, wd, acc2[i][0]);
                acc2[i][1] = f2fma(aA.y, wd, acc2[i][1]);
                acc2[i][2] = f2fma(aB.x, wd, acc2[i][2]);
                acc2[i][3] = f2fma(aB.y, wd, acc2[i][3]);
            }
        }
        __syncthreads();
    }

    float* gout = g_gi + (size_t)t * G3 * Bsz;
#pragma unroll
    for (int i = 0; i < 8; i++) {
        int c = (i < 4) ? (c0 + ty * 4 + i) : (c0 + 64 + ty * 4 + (i - 4));
        float bv = bias[c];
        float a0, a1, a2, a3, a4, a5, a6, a7;
        up2(acc2[i][0], a0, a1); up2(acc2[i][1], a2, a3);
        up2(acc2[i][2], a4, a5); up2(acc2[i][3], a6, a7);
        float4 o1 = make_float4(a0 + bv, a1 + bv, a2 + bv, a3 + bv);
        float4 o2 = make_float4(a4 + bv, a5 + bv, a6 + bv, a7 + bv);
        *(float4*)(gout + (size_t)c * Bsz + tx * 4)      = o1;
        *(float4*)(gout + (size_t)c * Bsz + 64 + tx * 4) = o2;
    }
}

// ---------------- persistent GRU recurrence ----------------
// 128 blocks x 512 threads. Block tile: 32 b x 8 j (24 gate rows).
// Thread: bq = tid&7 (4 batches via 2x f32x2), j = (tid>>3)&7, kq = tid>>6 (K/8 = 32 k).
// Weights duplicated as f32x2 pairs in SMEM. Two-stage SMEM reduction over kq.
__global__ __launch_bounds__(512) void gru_recur_kernel(
    const float* __restrict__ w_hh, const float* __restrict__ b_hh,
    const float* __restrict__ h0all, int layer)
{
    extern __shared__ __align__(16) char smraw[];
    u64*   w2_s  = (u64*)smraw;          // 24*258 = 6192 u64
    u64*   red_s = w2_s + 6192;          // 8 kq * 384 = 3072 u64
    float* h_s   = (float*)(red_s + 3072); // 256 k * 32 b = 8192 floats
    float* red2  = h_s + 8192;           // 768 floats
    float* bh_s  = red2 + 768;           // 24 (+pad)

    const int tid = threadIdx.x;
    const int bt = blockIdx.x >> 5;
    const int ht = blockIdx.x & 31;
    const int b0 = bt * 32;
    const int j0 = ht * 8;

    float* hseq = layer ? g_hseq1 : g_hseq0;

    // duplicated persistent weights
    for (int idx = tid; idx < 6144; idx += 512) {
        int gj = idx >> 8;            // 0..23
        int k  = idx & 255;
        int g  = gj >> 3, j = gj & 7;
        w2_s[gj * W2S + k] = dup2(w_hh[(size_t)(g * 256 + j0 + j) * 256 + k]);
    }
    if (tid < 24) {
        int g = tid >> 3, j = tid & 7;
        bh_s[tid] = b_hh[g * 256 + j0 + j];
    }

    unsigned gen = g_bar_gen;
    __syncthreads();

    const int bq = tid & 7;
    const int j  = (tid >> 3) & 7;
    const int kq = tid >> 6;
    const int kbase = kq * 32;

    const u64* wrp = w2_s + (0 + j) * W2S + kbase;
    const u64* wzp = w2_s + (8 + j) * W2S + kbase;
    const u64* wnp = w2_s + (16 + j) * W2S + kbase;
    const float* hb = h_s + kbase * 32 + bq * 4;

    // activation-thread mapping (tid < 256): ab = batch, aj = hidden unit
    const int ab = tid & 31;
    const int aj = (tid >> 5) & 7;
    const size_t gidx = (size_t)(j0 + aj) * Bsz + b0 + ab;

    float cir = 0.f, ciz = 0.f, cin_ = 0.f;
    if (tid < 256) {
        cir  = g_gi[gidx];
        ciz  = g_gi[32768 + gidx];
        cin_ = g_gi[65536 + gidx];
    }

    for (int t = 0; t < Lseq; t++) {
        // ---- stage h_prev into h_s[k][b(32)] ----
        if (t == 0) {
            const float* h0g = h0all + (size_t)layer * Bsz * Hd;  // [b][k]
            for (int i = tid; i < 8192; i += 512) {
                int k = i >> 5, bb = i & 31;
                h_s[k * 32 + bb] = h0g[(size_t)(b0 + bb) * 256 + k];
            }
        } else {
            const float* src = hseq + (size_t)(t - 1) * (Hd * Bsz);
#pragma unroll
            for (int u = 0; u < 4; u++) {
                int i = tid + u * 512;
                int k = i >> 3, c = i & 7;
                float4 v = *(const float4*)(src + (size_t)k * Bsz + b0 + c * 4);
                *(float4*)(h_s + k * 32 + c * 4) = v;
            }
        }
        __syncthreads();

        // ---- partial dot over this thread's 32 k's (f32x2 over batch) ----
        u64 ar0 = 0, ar1 = 0, az0 = 0, az1 = 0, an0 = 0, an1 = 0;
#pragma unroll
        for (int i = 0; i < 32; i += 2) {
            ulonglong2 ha = *(const ulonglong2*)(hb + i * 32);        // k=i,   4 b
            ulonglong2 hc = *(const ulonglong2*)(hb + i * 32 + 32);   // k=i+1, 4 b
            ulonglong2 wr = *(const ulonglong2*)(wrp + i);            // dup w, k=i / i+1
            ulonglong2 wz = *(const ulonglong2*)(wzp + i);
            ulonglong2 wn = *(const ulonglong2*)(wnp + i);
            ar0 = f2fma(ha.x, wr.x, ar0); ar1 = f2fma(ha.y, wr.x, ar1);
            ar0 = f2fma(hc.x, wr.y, ar0); ar1 = f2fma(hc.y, wr.y, ar1);
            az0 = f2fma(ha.x, wz.x, az0); az1 = f2fma(ha.y, wz.x, az1);
            az0 = f2fma(hc.x, wz.y, az0); az1 = f2fma(hc.y, wz.y, az1);
            an0 = f2fma(ha.x, wn.x, an0); an1 = f2fma(ha.y, wn.x, an1);
            an0 = f2fma(hc.x, wn.y, an0); an1 = f2fma(hc.y, wn.y, an1);
        }

        // ---- write partials: red[kq][g][j][bq][2] ----
        {
            u64* rb = red_s + (size_t)kq * 384 + (j * 8 + bq) * 2;
            *(ulonglong2*)(rb)       = make_ulonglong2(ar0, ar1);
            *(ulonglong2*)(rb + 128) = make_ulonglong2(az0, az1);
            *(ulonglong2*)(rb + 256) = make_ulonglong2(an0, an1);
        }
        __syncthreads();

        // ---- reduce over kq: 192 threads, one per (g, j, bq) ----
        if (tid < 192) {
            u64 s0 = 0, s1 = 0;
            const u64* base = red_s + tid * 2;
#pragma unroll
            for (int q = 0; q < 8; q++) {
                ulonglong2 v = *(const ulonglong2*)(base + q * 384);
                s0 = f2add(s0, v.x);
                s1 = f2add(s1, v.y);
            }
            int g = tid >> 6, jj = (tid >> 3) & 7, bb = tid & 7;
            float l0, h0f, l1, h1f;
            up2(s0, l0, h0f); up2(s1, l1, h1f);
            *(float4*)(red2 + (g * 8 + jj) * 32 + bb * 4) = make_float4(l0, h0f, l1, h1f);
        }
        __syncthreads();

        // ---- activation + write hnew: 256 threads (b, j) ----
        if (tid < 256) {
            float gr = red2[aj * 32 + ab]        + bh_s[aj];
            float gz = red2[(8 + aj) * 32 + ab]  + bh_s[8 + aj];
            float gn = red2[(16 + aj) * 32 + ab] + bh_s[16 + aj];
            float r = 1.0f / (1.0f + __expf(-(cir + gr)));
            float z = 1.0f / (1.0f + __expf(-(ciz + gz)));
            float n = tanhf(cin_ + r * gn);
            float hprev = h_s[(j0 + aj) * 32 + ab];
            float hnew = (1.0f - z) * n + z * hprev;
            hseq[(size_t)t * (Hd * Bsz) + (size_t)(j0 + aj) * Bsz + b0 + ab] = hnew;
        }
        __syncthreads();

        // ---- grid barrier; prefetch next gi during skew ----
        unsigned target = gen + 1;
        if (tid == 0) {
            __threadfence();
            if (atomicAdd(&g_bar_count, 1u) == RBLK - 1u) {
                atomicExch(&g_bar_count, 0u);
                __threadfence();
                g_bar_gen = target;
            }
        }
        if (tid < 256 && t + 1 < Lseq) {
            const float* gi_n = g_gi + (size_t)(t + 1) * (G3 * Bsz);
            cir  = gi_n[gidx];
            ciz  = gi_n[32768 + gidx];
            cin_ = gi_n[65536 + gidx];
        }
        if (tid == 0) {
            while (g_bar_gen != target) { }
        }
        gen = target;
        __syncthreads();
    }
}

// ---------------- transpose g_hseq1 [t][h][b] -> out [b][t][h] ----------------
__global__ __launch_bounds__(256) void transpose_out_kernel(float* __restrict__ out)
{
    __shared__ float tile[32 * 129];
    const int t  = blockIdx.y;
    const int h0 = blockIdx.x * 32;
    const int tid = threadIdx.x;
    const float* src = g_hseq1 + (size_t)t * (Hd * Bsz) + (size_t)h0 * Bsz;

    for (int idx = tid; idx < 4096; idx += 256) {
        int hh = idx >> 7, bb = idx & 127;
        tile[hh * 129 + bb] = src[idx];
    }
    __syncthreads();
    for (int idx = tid; idx < 4096; idx += 256) {
        int bb = idx >> 5, hh = idx & 31;
        out[(size_t)bb * Lseq * Hd + (size_t)t * Hd + h0 + hh] = tile[hh * 129 + bb];
    }
}

// ---------------- final hidden states ----------------
__global__ __launch_bounds__(256) void hn_kernel(float* __restrict__ out)
{
    int idx = blockIdx.x * blockDim.x + threadIdx.x;  // 0..65535
    int layer = idx >> 15;
    int b = (idx >> 8) & 127;
    int h = idx & 255;
    const float* hs = layer ? g_hseq1 : g_hseq0;
    out[(size_t)Bsz * Lseq * Hd + idx] =
        hs[(size_t)(Lseq - 1) * (Hd * Bsz) + (size_t)h * Bsz + b];
}

// ---------------- launcher ----------------
extern "C" void kernel_launch(void* const* d_in, const int* in_sizes, int n_in,
                              void* d_out, int out_size)
{
    const float* x     = (const float*)d_in[0];
    const float* h0    = (const float*)d_in[1];
    const float* w_ih0 = (const float*)d_in[2];
    const float* w_hh0 = (const float*)d_in[3];
    const float* b_ih0 = (const float*)d_in[4];
    const float* b_hh0 = (const float*)d_in[5];
    const float* w_ih1 = (const float*)d_in[6];
    const float* w_hh1 = (const float*)d_in[7];
    const float* b_ih1 = (const float*)d_in[8];
    const float* b_hh1 = (const float*)d_in[9];
    float* out = (float*)d_out;

    const size_t smem = (6192 + 3072) * sizeof(u64) + (8192 + 768 + 32) * sizeof(float);
    cudaFuncSetAttribute(gru_recur_kernel,
                         cudaFuncAttributeMaxDynamicSharedMemorySize, (int)smem);

    gi_gemm_kernel<<<dim3(6, Lseq), 256>>>(x, w_ih0, b_ih0, 0);
    gru_recur_kernel<<<RBLK, 512, smem>>>(w_hh0, b_hh0, h0, 0);
    gi_gemm_kernel<<<dim3(6, Lseq), 256>>>(x, w_ih1, b_ih1, 1);
    gru_recur_kernel<<<RBLK, 512, smem>>>(w_hh1, b_hh1, h0, 1);
    transpose_out_kernel<<<dim3(8, Lseq), 256>>>(out);
    if (out_size >= (int)((size_t)Bsz * Lseq * Hd + 2 * Bsz * Hd))
        hn_kernel<<<256, 256>>>(out);
}